// round 3
// baseline (speedup 1.0000x reference)
#include <cuda_runtime.h>
#include <math_constants.h>

// Problem constants
#define Bv   4
#define Tv   2048
#define Cv   1024
#define Hv   16
#define HDv  64
#define NTOK (Bv * Tv)      // 8192
#define C3   (3 * Cv)       // 3072

// Scratch (static device globals -- allocation-guard safe)
__device__ float g_q[(size_t)Bv * Hv * Tv * HDv];   // [B,H,T,HD]
__device__ float g_k[(size_t)Bv * Hv * Tv * HDv];
__device__ float g_v[(size_t)Bv * Hv * Tv * HDv];
__device__ float g_att[(size_t)NTOK * Cv];          // [B,T,C]

// ---------------------------------------------------------------------------
// Tiled fp32 GEMM: C[M,N] = A[M,K] @ B[K,N]
// BM=BN=64, BK=16, 256 threads, 4x4 microtile per thread.
// A stored transposed in smem so both microtile operand loads are float4.
// MODE 0: A = x param, scatter output into g_q/g_k/g_v ([B,H,T,HD] layout)
// MODE 1: A = g_att,   write output row-major to Cout
// ---------------------------------------------------------------------------
template <int MODE>
__global__ __launch_bounds__(256)
void gemm64_kernel(const float* __restrict__ Aparam,
                   const float* __restrict__ Bm,
                   float* __restrict__ Cout,
                   int M, int N, int K)
{
    __shared__ float Ast[16][68];   // [k][m], pad 4 (row = 272B, 16B-aligned)
    __shared__ float Bs[16][64];    // [k][n]

    const float* A = (MODE == 0) ? Aparam : (const float*)g_att;

    const int tid = threadIdx.x;
    const int tx  = tid & 15;
    const int ty  = tid >> 4;
    const int m0  = blockIdx.y * 64;
    const int n0  = blockIdx.x * 64;

    // Global-load mappings
    const int rowA = tid >> 2;            // 0..63
    const int ka   = (tid & 3) << 2;      // 0,4,8,12
    const int kb   = tid >> 4;            // 0..15
    const int jb   = (tid & 15) << 2;     // 0..60

    const float* aptr = A  + (size_t)(m0 + rowA) * K + ka;
    const float* bptr = Bm + (size_t)kb * N + n0 + jb;

    float acc[4][4] = {};

    // Prefetch first tile
    float4 a4 = *(const float4*)(aptr);
    float4 b4 = *(const float4*)(bptr);

    for (int kt = 0; kt < K; kt += 16) {
        __syncthreads();
        Ast[ka + 0][rowA] = a4.x;
        Ast[ka + 1][rowA] = a4.y;
        Ast[ka + 2][rowA] = a4.z;
        Ast[ka + 3][rowA] = a4.w;
        *(float4*)(&Bs[kb][jb]) = b4;
        __syncthreads();

        if (kt + 16 < K) {  // prefetch next tile (latency overlapped w/ compute)
            a4 = *(const float4*)(aptr + kt + 16);
            b4 = *(const float4*)(bptr + (size_t)(kt + 16) * N);
        }

        #pragma unroll
        for (int k = 0; k < 16; ++k) {
            const float4 av = *(const float4*)(&Ast[k][ty << 2]); // broadcast
            const float4 bv = *(const float4*)(&Bs[k][tx << 2]);  // 2-way (min)
            const float a[4]  = {av.x, av.y, av.z, av.w};
            const float bb[4] = {bv.x, bv.y, bv.z, bv.w};
            #pragma unroll
            for (int i = 0; i < 4; ++i)
                #pragma unroll
                for (int j = 0; j < 4; ++j)
                    acc[i][j] = fmaf(a[i], bb[j], acc[i][j]);
        }
    }

    if (MODE == 0) {
        // Scatter into q/k/v head-split layout. n0 is a multiple of 64, so
        // section (q/k/v) and head are constant per block; d = tx*4 + j.
        const int sec = n0 >> 10;            // 0:q 1:k 2:v
        const int h   = (n0 & 1023) >> 6;
        float* dst = (sec == 0) ? g_q : (sec == 1) ? g_k : g_v;
        #pragma unroll
        for (int i = 0; i < 4; ++i) {
            const int m = m0 + (ty << 2) + i;
            const int b = m >> 11;           // /T
            const int t = m & 2047;          // %T
            float4 v = make_float4(acc[i][0], acc[i][1], acc[i][2], acc[i][3]);
            *(float4*)(dst + (((size_t)b * Hv + h) * Tv + t) * HDv + (tx << 2)) = v;
        }
    } else {
        #pragma unroll
        for (int i = 0; i < 4; ++i) {
            const int m = m0 + (ty << 2) + i;
            float4 v = make_float4(acc[i][0], acc[i][1], acc[i][2], acc[i][3]);
            *(float4*)(Cout + (size_t)m * N + n0 + (tx << 2)) = v;
        }
    }
}

// ---------------------------------------------------------------------------
// Causal flash attention, fp32, 64x64 tiles, online softmax.
// One block per (b,h,q-tile of 64 rows). 256 threads, 4x4 microtiles.
// smem: Qs (q rows, d-major), KVs (K stored [d][key], reused for V [key][d]),
//       Ss (scores/P; first 16 cols aliased as reduction scratch).
// Exactly 48KB static smem -> 3-4 CTAs/SM.
// ---------------------------------------------------------------------------
__global__ __launch_bounds__(256)
void attn_kernel()
{
    __shared__ float Qs[64][64];
    __shared__ float KVs[64][64];
    __shared__ float Ss[64][64];

    const int tid = threadIdx.x;
    const int tx  = tid & 15;
    const int ty  = tid >> 4;
    // Launch longest q-tiles first (more k-tiles) for wave balance
    const int qt = (int)gridDim.x - 1 - (int)blockIdx.x;
    const int bh = blockIdx.y;
    const int b  = bh >> 4;
    const int h  = bh & 15;
    const size_t plane = (size_t)bh * Tv * HDv;
    const int q0 = qt * 64;

    // Load Q tile (contiguous 16KB chunk) -- flat float4 copy
    {
        const float4* src = (const float4*)(g_q + plane + (size_t)q0 * HDv);
        float4* dst = (float4*)&Qs[0][0];
        #pragma unroll
        for (int c = 0; c < 4; ++c) dst[tid + 256 * c] = src[tid + 256 * c];
    }

    float o[4][4] = {};
    float mrow[4] = {-CUDART_INF_F, -CUDART_INF_F, -CUDART_INF_F, -CUDART_INF_F};
    float lrow[4] = {};

    const int keyl = tid & 63;        // for K transpose load
    const int dbl  = (tid >> 6) << 4; // 0,16,32,48

    for (int kt = 0; kt <= qt; ++kt) {
        const int k0 = kt * 64;

        __syncthreads();  // guards KVs/Ss reuse from previous iteration

        // Load K tile transposed: KVs[d][key]
        {
            const float* ks = g_k + plane + (size_t)(k0 + keyl) * HDv + dbl;
            #pragma unroll
            for (int c = 0; c < 4; ++c) {
                const float4 kv4 = *(const float4*)(ks + (c << 2));
                KVs[dbl + (c << 2) + 0][keyl] = kv4.x;
                KVs[dbl + (c << 2) + 1][keyl] = kv4.y;
                KVs[dbl + (c << 2) + 2][keyl] = kv4.z;
                KVs[dbl + (c << 2) + 3][keyl] = kv4.w;
            }
        }
        __syncthreads();

        // S = Q K^T (4x4 microtile). KVs row index d is warp-uniform -> float4
        // loads hit the 2-way structural minimum; Q reads are broadcast.
        float s[4][4] = {};
        #pragma unroll 16
        for (int d = 0; d < 64; ++d) {
            const float4 kv = *(const float4*)(&KVs[d][tx << 2]);
            const float qv0 = Qs[(ty << 2) + 0][d];
            const float qv1 = Qs[(ty << 2) + 1][d];
            const float qv2 = Qs[(ty << 2) + 2][d];
            const float qv3 = Qs[(ty << 2) + 3][d];
            s[0][0] = fmaf(qv0, kv.x, s[0][0]); s[0][1] = fmaf(qv0, kv.y, s[0][1]);
            s[0][2] = fmaf(qv0, kv.z, s[0][2]); s[0][3] = fmaf(qv0, kv.w, s[0][3]);
            s[1][0] = fmaf(qv1, kv.x, s[1][0]); s[1][1] = fmaf(qv1, kv.y, s[1][1]);
            s[1][2] = fmaf(qv1, kv.z, s[1][2]); s[1][3] = fmaf(qv1, kv.w, s[1][3]);
            s[2][0] = fmaf(qv2, kv.x, s[2][0]); s[2][1] = fmaf(qv2, kv.y, s[2][1]);
            s[2][2] = fmaf(qv2, kv.z, s[2][2]); s[2][3] = fmaf(qv2, kv.w, s[2][3]);
            s[3][0] = fmaf(qv3, kv.x, s[3][0]); s[3][1] = fmaf(qv3, kv.y, s[3][1]);
            s[3][2] = fmaf(qv3, kv.z, s[3][2]); s[3][3] = fmaf(qv3, kv.w, s[3][3]);
        }

        // Scale + causal mask (tiles with kt < qt are never masked; condition
        // is compile-time-cheap so apply uniformly)
        #pragma unroll
        for (int i = 0; i < 4; ++i) {
            const int qg = q0 + (ty << 2) + i;
            #pragma unroll
            for (int j = 0; j < 4; ++j) {
                const int kg = k0 + (tx << 2) + j;
                const float v = s[i][j] * 0.125f;  // 1/sqrt(64)
                s[i][j] = (kg > qg) ? -CUDART_INF_F : v;
            }
        }

        // Row max: per-thread partial -> smem (aliased onto Ss) -> redundant
        // full reduction in every thread (keeps m/l consistent in registers,
        // no extra smem arrays).
        #pragma unroll
        for (int i = 0; i < 4; ++i)
            Ss[(ty << 2) + i][tx] =
                fmaxf(fmaxf(s[i][0], s[i][1]), fmaxf(s[i][2], s[i][3]));
        __syncthreads();

        float mnew[4], alpha[4];
        #pragma unroll
        for (int i = 0; i < 4; ++i) {
            float mm = mrow[i];
            #pragma unroll
            for (int c = 0; c < 16; ++c)
                mm = fmaxf(mm, Ss[(ty << 2) + i][c]);
            mnew[i]  = mm;
            alpha[i] = __expf(mrow[i] - mm);  // exp(-inf)=0 on first tile
            mrow[i]  = mm;
        }
        __syncthreads();  // all max-reads done before sum partials overwrite

        // exp + row-sum partials
        #pragma unroll
        for (int i = 0; i < 4; ++i) {
            float t = 0.f;
            #pragma unroll
            for (int j = 0; j < 4; ++j) {
                const float p = __expf(s[i][j] - mnew[i]);  // masked -> 0
                s[i][j] = p;
                t += p;
            }
            Ss[(ty << 2) + i][tx] = t;
        }
        __syncthreads();

        #pragma unroll
        for (int i = 0; i < 4; ++i) {
            float t = 0.f;
            #pragma unroll
            for (int c = 0; c < 16; ++c)
                t += Ss[(ty << 2) + i][c];
            lrow[i] = lrow[i] * alpha[i] + t;
            #pragma unroll
            for (int j = 0; j < 4; ++j)
                o[i][j] *= alpha[i];
        }
        __syncthreads();  // all sum-reads done before P overwrites Ss

        // Write P into Ss; load V tile into KVs (K reads are done)
        #pragma unroll
        for (int i = 0; i < 4; ++i) {
            float4 pv = make_float4(s[i][0], s[i][1], s[i][2], s[i][3]);
            *(float4*)(&Ss[(ty << 2) + i][tx << 2]) = pv;
        }
        {
            const float4* vs = (const float4*)(g_v + plane + (size_t)k0 * HDv);
            float4* vd = (float4*)&KVs[0][0];
            #pragma unroll
            for (int c = 0; c < 4; ++c) vd[tid + 256 * c] = vs[tid + 256 * c];
        }
        __syncthreads();

        // O += P @ V  (V row index k warp-uniform -> float4, 2-way min)
        #pragma unroll 16
        for (int k = 0; k < 64; ++k) {
            const float4 vv = *(const float4*)(&KVs[k][tx << 2]);
            const float p0 = Ss[(ty << 2) + 0][k];
            const float p1 = Ss[(ty << 2) + 1][k];
            const float p2 = Ss[(ty << 2) + 2][k];
            const float p3 = Ss[(ty << 2) + 3][k];
            o[0][0] = fmaf(p0, vv.x, o[0][0]); o[0][1] = fmaf(p0, vv.y, o[0][1]);
            o[0][2] = fmaf(p0, vv.z, o[0][2]); o[0][3] = fmaf(p0, vv.w, o[0][3]);
            o[1][0] = fmaf(p1, vv.x, o[1][0]); o[1][1] = fmaf(p1, vv.y, o[1][1]);
            o[1][2] = fmaf(p1, vv.z, o[1][2]); o[1][3] = fmaf(p1, vv.w, o[1][3]);
            o[2][0] = fmaf(p2, vv.x, o[2][0]); o[2][1] = fmaf(p2, vv.y, o[2][1]);
            o[2][2] = fmaf(p2, vv.z, o[2][2]); o[2][3] = fmaf(p2, vv.w, o[2][3]);
            o[3][0] = fmaf(p3, vv.x, o[3][0]); o[3][1] = fmaf(p3, vv.y, o[3][1]);
            o[3][2] = fmaf(p3, vv.z, o[3][2]); o[3][3] = fmaf(p3, vv.w, o[3][3]);
        }
    }

    // Epilogue: normalize, write to g_att in [B,T,C] layout (merged heads)
    #pragma unroll
    for (int i = 0; i < 4; ++i) {
        const float inv = 1.0f / lrow[i];
        const int t = q0 + (ty << 2) + i;
        float4 ov = make_float4(o[i][0] * inv, o[i][1] * inv,
                                o[i][2] * inv, o[i][3] * inv);
        *(float4*)(g_att + ((size_t)(b * Tv + t)) * Cv + h * HDv + (tx << 2)) = ov;
    }
}

// ---------------------------------------------------------------------------
extern "C" void kernel_launch(void* const* d_in, const int* in_sizes, int n_in,
                              void* d_out, int out_size)
{
    const float* x      = (const float*)d_in[0];   // [B,T,C]
    const float* w_qkv  = (const float*)d_in[1];   // [C, 3C]
    const float* w_proj = (const float*)d_in[2];   // [C, C]
    float* out = (float*)d_out;                    // [B,T,C]

    const dim3 blk(256);

    // 1) qkv = x @ w_qkv, scattered into g_q/g_k/g_v [B,H,T,HD]
    gemm64_kernel<0><<<dim3(C3 / 64, NTOK / 64), blk>>>(
        x, w_qkv, nullptr, NTOK, C3, Cv);

    // 2) causal flash attention -> g_att [B,T,C]
    attn_kernel<<<dim3(Tv / 64, Bv * Hv), blk>>>();

    // 3) out = g_att @ w_proj
    gemm64_kernel<1><<<dim3(Cv / 64, NTOK / 64), blk>>>(
        nullptr, w_proj, out, NTOK, Cv, Cv);
}

// round 4
// speedup vs baseline: 1.1272x; 1.1272x over previous
#include <cuda_runtime.h>
#include <math_constants.h>

// Problem constants
#define Bv   4
#define Tv   2048
#define Cv   1024
#define Hv   16
#define HDv  64
#define NTOK (Bv * Tv)      // 8192
#define C3   (3 * Cv)       // 3072

// Scratch (static device globals -- allocation-guard safe)
__device__ float g_q[(size_t)Bv * Hv * Tv * HDv];   // [B,H,T,HD]
__device__ float g_k[(size_t)Bv * Hv * Tv * HDv];
__device__ float g_v[(size_t)Bv * Hv * Tv * HDv];
__device__ float g_att[(size_t)NTOK * Cv];          // [B,T,C]

// ---------------------------------------------------------------------------
// Tiled fp32 GEMM: C[M,N] = A[M,K] @ B[K,N]
// BM=BN=128, BK=16, 256 threads, 8x8 microtile per thread.
// 16 smem words per 64 FMAs = 4 FLOP/word (2x the old 4x4 kernel).
// MODE 0: A = x param, scatter output into g_q/g_k/g_v ([B,H,T,HD] layout)
// MODE 1: A = g_att,   write output row-major to Cout
// ---------------------------------------------------------------------------
template <int MODE>
__global__ __launch_bounds__(256, 2)
void gemm128_kernel(const float* __restrict__ Aparam,
                    const float* __restrict__ Bm,
                    float* __restrict__ Cout,
                    int M, int N, int K)
{
    __shared__ float Ast[16][132];  // [k][m] transposed, pad 4
    __shared__ float Bs[16][128];   // [k][n]

    const float* A = (MODE == 0) ? Aparam : (const float*)g_att;

    const int tid = threadIdx.x;
    const int tx  = tid & 15;        // n-group (8 cols)
    const int ty  = tid >> 4;        // m-group (8 rows)
    const int m0  = blockIdx.y * 128;
    const int n0  = blockIdx.x * 128;

    // Staging maps: A tile 128x16 (2 float4/thread), B tile 16x128 (2 float4/thread)
    const int arow = tid >> 1;             // 0..127
    const int ak0  = (tid & 1) << 3;       // 0 or 8
    const int brow = tid >> 4;             // 0..15
    const int bcol = (tid & 15) << 3;      // 0..120

    const float* aptr = A  + (size_t)(m0 + arow) * K + ak0;
    const float* bptr = Bm + (size_t)brow * N + n0 + bcol;

    float acc[8][8] = {};

    // Prefetch first tile into registers
    float4 a0 = *(const float4*)(aptr);
    float4 a1 = *(const float4*)(aptr + 4);
    float4 b0 = *(const float4*)(bptr);
    float4 b1 = *(const float4*)(bptr + 4);

    for (int kt = 0; kt < K; kt += 16) {
        __syncthreads();
        Ast[ak0 + 0][arow] = a0.x;  Ast[ak0 + 1][arow] = a0.y;
        Ast[ak0 + 2][arow] = a0.z;  Ast[ak0 + 3][arow] = a0.w;
        Ast[ak0 + 4][arow] = a1.x;  Ast[ak0 + 5][arow] = a1.y;
        Ast[ak0 + 6][arow] = a1.z;  Ast[ak0 + 7][arow] = a1.w;
        *(float4*)(&Bs[brow][bcol])     = b0;
        *(float4*)(&Bs[brow][bcol + 4]) = b1;
        __syncthreads();

        if (kt + 16 < K) {  // prefetch next tile
            a0 = *(const float4*)(aptr + kt + 16);
            a1 = *(const float4*)(aptr + kt + 20);
            b0 = *(const float4*)(bptr + (size_t)(kt + 16) * N);
            b1 = *(const float4*)(bptr + (size_t)(kt + 16) * N + 4);
        }

        #pragma unroll
        for (int k = 0; k < 16; ++k) {
            const float4 af0 = *(const float4*)(&Ast[k][ty << 3]);
            const float4 af1 = *(const float4*)(&Ast[k][(ty << 3) + 4]);
            const float4 bf0 = *(const float4*)(&Bs[k][tx << 3]);
            const float4 bf1 = *(const float4*)(&Bs[k][(tx << 3) + 4]);
            const float a[8] = {af0.x, af0.y, af0.z, af0.w,
                                af1.x, af1.y, af1.z, af1.w};
            const float b[8] = {bf0.x, bf0.y, bf0.z, bf0.w,
                                bf1.x, bf1.y, bf1.z, bf1.w};
            #pragma unroll
            for (int i = 0; i < 8; ++i)
                #pragma unroll
                for (int j = 0; j < 8; ++j)
                    acc[i][j] = fmaf(a[i], b[j], acc[i][j]);
        }
    }

    if (MODE == 0) {
        // Scatter into q/k/v head-split layout [B,H,T,HD].
        // Block spans 128 columns = 2 heads; one section (q/k/v) per block.
        const int nb  = n0 + (tx << 3);      // thread's first output column
        const int sec = nb >> 10;            // 0:q 1:k 2:v
        const int h   = (nb & 1023) >> 6;
        const int d0  = nb & 63;             // 0..56, 8-wide within one head
        float* dst = (sec == 0) ? g_q : (sec == 1) ? g_k : g_v;
        #pragma unroll
        for (int i = 0; i < 8; ++i) {
            const int m = m0 + (ty << 3) + i;
            const int b = m >> 11;           // /T
            const int t = m & 2047;          // %T
            float* p = dst + (((size_t)b * Hv + h) * Tv + t) * HDv + d0;
            *(float4*)(p)     = make_float4(acc[i][0], acc[i][1], acc[i][2], acc[i][3]);
            *(float4*)(p + 4) = make_float4(acc[i][4], acc[i][5], acc[i][6], acc[i][7]);
        }
    } else {
        #pragma unroll
        for (int i = 0; i < 8; ++i) {
            const int m = m0 + (ty << 3) + i;
            float* p = Cout + (size_t)m * N + n0 + (tx << 3);
            *(float4*)(p)     = make_float4(acc[i][0], acc[i][1], acc[i][2], acc[i][3]);
            *(float4*)(p + 4) = make_float4(acc[i][4], acc[i][5], acc[i][6], acc[i][7]);
        }
    }
}

// ---------------------------------------------------------------------------
// Causal flash attention, fp32, 128(q) x 64(k) tiles, online softmax.
// 256 threads: tx=tid&15 -> 4 keys / 4 d-cols, ty=tid>>4 -> 8 q rows.
// Q stored d-major in smem (float4 loads); softmax reductions via shfl_xor
// within half-warps (threads sharing a row group differ only in lane bits 0-3).
// Separate K/V buffers -> 3 barriers per k-tile.
// Dynamic smem: Qst 32KB + Ks 16KB + Vs 16KB + Ss 32KB = 96KB -> 2 CTAs/SM.
// ---------------------------------------------------------------------------
#define ATTN_SMEM_BYTES ((64*128 + 64*64 + 64*64 + 128*64) * 4)

__global__ __launch_bounds__(256, 2)
void attn_kernel()
{
    extern __shared__ float sm[];
    float* Qst = sm;                    // [d:64][q:128]
    float* Ks  = Qst + 64 * 128;        // [d:64][key:64]
    float* Vs  = Ks  + 64 * 64;         // [key:64][d:64]
    float* Ss  = Vs  + 64 * 64;         // [q:128][key:64]

    const int tid = threadIdx.x;
    const int tx  = tid & 15;
    const int ty  = tid >> 4;
    // Longest q-tiles first for wave balance
    const int qt = (int)gridDim.x - 1 - (int)blockIdx.x;
    const int bh = blockIdx.y;
    const int b  = bh >> 4;
    const int h  = bh & 15;
    const size_t plane = (size_t)bh * Tv * HDv;
    const int q0 = qt * 128;

    // Load Q tile transposed: Qst[d][qrow]
    {
        const int qrow = tid & 127;
        const int dh   = (tid >> 7) << 5;   // 0 or 32
        const float* qsrc = g_q + plane + (size_t)(q0 + qrow) * HDv + dh;
        #pragma unroll
        for (int c = 0; c < 8; ++c) {
            const float4 v = *(const float4*)(qsrc + (c << 2));
            Qst[(dh + (c << 2) + 0) * 128 + qrow] = v.x;
            Qst[(dh + (c << 2) + 1) * 128 + qrow] = v.y;
            Qst[(dh + (c << 2) + 2) * 128 + qrow] = v.z;
            Qst[(dh + (c << 2) + 3) * 128 + qrow] = v.w;
        }
    }

    float o[8][4] = {};
    float mrow[8], lrow[8] = {};
    #pragma unroll
    for (int i = 0; i < 8; ++i) { mrow[i] = -CUDART_INF_F; lrow[i] = 0.f; }

    const int keyl = tid & 63;
    const int dbl  = (tid >> 6) << 4;   // 0,16,32,48
    const int ktmax = 2 * qt + 1;       // last k-tile overlapping this q-tile

    for (int kt = 0; kt <= ktmax; ++kt) {
        const int k0 = kt * 64;

        __syncthreads();  // prev PV reads (Ss,Vs) and QK reads (Ks,Qst init) done

        // K tile transposed: Ks[d][key]
        {
            const float* ksrc = g_k + plane + (size_t)(k0 + keyl) * HDv + dbl;
            #pragma unroll
            for (int c = 0; c < 4; ++c) {
                const float4 v = *(const float4*)(ksrc + (c << 2));
                Ks[(dbl + (c << 2) + 0) * 64 + keyl] = v.x;
                Ks[(dbl + (c << 2) + 1) * 64 + keyl] = v.y;
                Ks[(dbl + (c << 2) + 2) * 64 + keyl] = v.z;
                Ks[(dbl + (c << 2) + 3) * 64 + keyl] = v.w;
            }
        }
        // V tile flat copy: Vs[key][d]
        {
            const float4* vsrc = (const float4*)(g_v + plane + (size_t)k0 * HDv);
            float4* vd = (float4*)Vs;
            #pragma unroll
            for (int c = 0; c < 4; ++c) vd[tid + 256 * c] = vsrc[tid + 256 * c];
        }
        __syncthreads();

        // S = Q K^T, 8x4 microtile: 3 x LDS.128 per d for 32 FMAs
        float s[8][4] = {};
        #pragma unroll 8
        for (int d = 0; d < 64; ++d) {
            const float4 kf  = *(const float4*)(&Ks[d * 64 + (tx << 2)]);
            const float4 qf0 = *(const float4*)(&Qst[d * 128 + (ty << 3)]);
            const float4 qf1 = *(const float4*)(&Qst[d * 128 + (ty << 3) + 4]);
            const float qa[8] = {qf0.x, qf0.y, qf0.z, qf0.w,
                                 qf1.x, qf1.y, qf1.z, qf1.w};
            #pragma unroll
            for (int i = 0; i < 8; ++i) {
                s[i][0] = fmaf(qa[i], kf.x, s[i][0]);
                s[i][1] = fmaf(qa[i], kf.y, s[i][1]);
                s[i][2] = fmaf(qa[i], kf.z, s[i][2]);
                s[i][3] = fmaf(qa[i], kf.w, s[i][3]);
            }
        }

        // Scale + causal mask + online softmax (shfl reductions across tx)
        #pragma unroll
        for (int i = 0; i < 8; ++i) {
            const int qg = q0 + (ty << 3) + i;
            const int kg = k0 + (tx << 2);
            #pragma unroll
            for (int j = 0; j < 4; ++j) {
                const float v = s[i][j] * 0.125f;   // 1/sqrt(64)
                s[i][j] = (kg + j > qg) ? -CUDART_INF_F : v;
            }
            float mx = fmaxf(fmaxf(s[i][0], s[i][1]), fmaxf(s[i][2], s[i][3]));
            #pragma unroll
            for (int off = 1; off < 16; off <<= 1)
                mx = fmaxf(mx, __shfl_xor_sync(0xffffffffu, mx, off));
            const float mnew  = fmaxf(mrow[i], mx);
            const float alpha = __expf(mrow[i] - mnew);  // exp(-inf)=0 first tile
            mrow[i] = mnew;

            float sum = 0.f;
            #pragma unroll
            for (int j = 0; j < 4; ++j) {
                const float p = __expf(s[i][j] - mnew);  // masked -> 0
                s[i][j] = p;
                sum += p;
            }
            #pragma unroll
            for (int off = 1; off < 16; off <<= 1)
                sum += __shfl_xor_sync(0xffffffffu, sum, off);
            lrow[i] = lrow[i] * alpha + sum;
            #pragma unroll
            for (int j = 0; j < 4; ++j) o[i][j] *= alpha;

            // Stage P into Ss for the PV GEMM
            *(float4*)(&Ss[((ty << 3) + i) * 64 + (tx << 2)]) =
                make_float4(s[i][0], s[i][1], s[i][2], s[i][3]);
        }
        __syncthreads();  // P + V visible to everyone

        // O += P @ V
        #pragma unroll 8
        for (int k = 0; k < 64; ++k) {
            const float4 vf = *(const float4*)(&Vs[k * 64 + (tx << 2)]);
            float p[8];
            #pragma unroll
            for (int i = 0; i < 8; ++i) p[i] = Ss[((ty << 3) + i) * 64 + k];
            #pragma unroll
            for (int i = 0; i < 8; ++i) {
                o[i][0] = fmaf(p[i], vf.x, o[i][0]);
                o[i][1] = fmaf(p[i], vf.y, o[i][1]);
                o[i][2] = fmaf(p[i], vf.z, o[i][2]);
                o[i][3] = fmaf(p[i], vf.w, o[i][3]);
            }
        }
    }

    // Epilogue: normalize, write [B,T,C] (merged heads)
    #pragma unroll
    for (int i = 0; i < 8; ++i) {
        const float inv = 1.0f / lrow[i];
        const int t = q0 + (ty << 3) + i;
        *(float4*)(g_att + ((size_t)(b * Tv + t)) * Cv + h * HDv + (tx << 2)) =
            make_float4(o[i][0] * inv, o[i][1] * inv, o[i][2] * inv, o[i][3] * inv);
    }
}

// ---------------------------------------------------------------------------
extern "C" void kernel_launch(void* const* d_in, const int* in_sizes, int n_in,
                              void* d_out, int out_size)
{
    const float* x      = (const float*)d_in[0];   // [B,T,C]
    const float* w_qkv  = (const float*)d_in[1];   // [C, 3C]
    const float* w_proj = (const float*)d_in[2];   // [C, C]
    float* out = (float*)d_out;                    // [B,T,C]

    // Opt-in >48KB dynamic smem for attention (idempotent, host-side, capturable)
    cudaFuncSetAttribute(attn_kernel,
                         cudaFuncAttributeMaxDynamicSharedMemorySize,
                         ATTN_SMEM_BYTES);

    const dim3 blk(256);

    // 1) qkv = x @ w_qkv, scattered into g_q/g_k/g_v [B,H,T,HD]
    gemm128_kernel<0><<<dim3(C3 / 128, NTOK / 128), blk>>>(
        x, w_qkv, nullptr, NTOK, C3, Cv);

    // 2) causal flash attention -> g_att [B,T,C]
    attn_kernel<<<dim3(Tv / 128, Bv * Hv), blk, ATTN_SMEM_BYTES>>>();

    // 3) out = g_att @ w_proj
    gemm128_kernel<1><<<dim3(Cv / 128, NTOK / 128), blk>>>(
        nullptr, w_proj, out, NTOK, Cv, Cv);
}

// round 5
// speedup vs baseline: 1.2995x; 1.1528x over previous
#include <cuda_runtime.h>
#include <math_constants.h>

// Problem constants
#define Bv   4
#define Tv   2048
#define Cv   1024
#define Hv   16
#define HDv  64
#define NTOK (Bv * Tv)      // 8192
#define C3   (3 * Cv)       // 3072

typedef unsigned long long u64t;

// ---- packed fp32x2 helpers (sm_103a FFMA2 path; bit-exact fp32) ----------
__device__ __forceinline__ u64t splat2(float x) {
    u64t r; asm("mov.b64 %0, {%1, %1};" : "=l"(r) : "f"(x)); return r;
}
__device__ __forceinline__ void fma2(u64t& d, u64t a, u64t b) {
    asm("fma.rn.f32x2 %0, %1, %2, %0;" : "+l"(d) : "l"(a), "l"(b));
}
__device__ __forceinline__ void mul2(u64t& d, u64t a) {
    asm("mul.rn.f32x2 %0, %0, %1;" : "+l"(d) : "l"(a));
}
__device__ __forceinline__ float2 unpack2(u64t v) {
    float2 f; asm("mov.b64 {%0, %1}, %2;" : "=f"(f.x), "=f"(f.y) : "l"(v)); return f;
}

// Scratch (static device globals -- allocation-guard safe)
__device__ float g_q[(size_t)Bv * Hv * Tv * HDv];   // [B,H,T,HD]
__device__ float g_k[(size_t)Bv * Hv * Tv * HDv];
__device__ float g_v[(size_t)Bv * Hv * Tv * HDv];
__device__ float g_att[(size_t)NTOK * Cv];          // [B,T,C]

// ---------------------------------------------------------------------------
// Tiled fp32 GEMM via packed f32x2: C[M,N] = A[M,K] @ B[K,N]
// BM=BN=128, BK=16, 256 threads, 8x8 microtile.
// Thread columns: {tx*4..+3} and {64+tx*4..+3} -> 16B-stride smem access
// (2-way minimum, kills the old 4-way conflict). B pairs come free from
// 128-bit loads; A splats go to the alu pipe.
// MODE 0: A = x param, scatter output into g_q/g_k/g_v ([B,H,T,HD] layout)
// MODE 1: A = g_att,   write output row-major to Cout
// ---------------------------------------------------------------------------
template <int MODE>
__global__ __launch_bounds__(256, 2)
void gemm128_kernel(const float* __restrict__ Aparam,
                    const float* __restrict__ Bm,
                    float* __restrict__ Cout,
                    int M, int N, int K)
{
    __shared__ float Ast[16][132];  // [k][m] transposed, pad 4
    __shared__ float Bs[16][128];   // [k][n]

    const float* A = (MODE == 0) ? Aparam : (const float*)g_att;

    const int tid = threadIdx.x;
    const int tx  = tid & 15;        // n-group
    const int ty  = tid >> 4;        // m-group (8 rows)
    const int m0  = blockIdx.y * 128;
    const int n0  = blockIdx.x * 128;

    // Staging maps
    const int arow = tid >> 1;             // 0..127
    const int ak0  = (tid & 1) << 3;       // 0 or 8
    const int brow = tid >> 4;             // 0..15
    const int bcol = (tid & 15) << 2;      // 0..60 (plus +64 twin)

    const float* aptr = A  + (size_t)(m0 + arow) * K + ak0;
    const float* bptr = Bm + (size_t)brow * N + n0 + bcol;

    // acc pairs: [i][0..1] -> cols tx*4+{0,1},{2,3}; [i][2..3] -> 64+tx*4+{0,1},{2,3}
    u64t acc[8][4] = {};

    // Prefetch first tile into registers
    float4 a0 = *(const float4*)(aptr);
    float4 a1 = *(const float4*)(aptr + 4);
    float4 b0 = *(const float4*)(bptr);
    float4 b1 = *(const float4*)(bptr + 64);

    for (int kt = 0; kt < K; kt += 16) {
        __syncthreads();
        Ast[ak0 + 0][arow] = a0.x;  Ast[ak0 + 1][arow] = a0.y;
        Ast[ak0 + 2][arow] = a0.z;  Ast[ak0 + 3][arow] = a0.w;
        Ast[ak0 + 4][arow] = a1.x;  Ast[ak0 + 5][arow] = a1.y;
        Ast[ak0 + 6][arow] = a1.z;  Ast[ak0 + 7][arow] = a1.w;
        *(float4*)(&Bs[brow][bcol])      = b0;
        *(float4*)(&Bs[brow][bcol + 64]) = b1;
        __syncthreads();

        if (kt + 16 < K) {  // prefetch next tile
            a0 = *(const float4*)(aptr + kt + 16);
            a1 = *(const float4*)(aptr + kt + 20);
            b0 = *(const float4*)(bptr + (size_t)(kt + 16) * N);
            b1 = *(const float4*)(bptr + (size_t)(kt + 16) * N + 64);
        }

        #pragma unroll
        for (int k = 0; k < 16; ++k) {
            const ulonglong2 bp0 = *(const ulonglong2*)(&Bs[k][tx << 2]);
            const ulonglong2 bp1 = *(const ulonglong2*)(&Bs[k][64 + (tx << 2)]);
            const float4 af0 = *(const float4*)(&Ast[k][ty << 3]);      // broadcast
            const float4 af1 = *(const float4*)(&Ast[k][(ty << 3) + 4]);
            const float a[8] = {af0.x, af0.y, af0.z, af0.w,
                                af1.x, af1.y, af1.z, af1.w};
            #pragma unroll
            for (int i = 0; i < 8; ++i) {
                const u64t as = splat2(a[i]);       // alu pipe
                fma2(acc[i][0], as, bp0.x);
                fma2(acc[i][1], as, bp0.y);
                fma2(acc[i][2], as, bp1.x);
                fma2(acc[i][3], as, bp1.y);
            }
        }
    }

    if (MODE == 0) {
        // Scatter into q/k/v head-split layout [B,H,T,HD].
        // Column group 0 lives in head h0, group 1 in head h0+1 (same section).
        const int sec = n0 >> 10;            // 0:q 1:k 2:v
        const int h0  = (n0 & 1023) >> 6;
        float* dst = (sec == 0) ? g_q : (sec == 1) ? g_k : g_v;
        #pragma unroll
        for (int i = 0; i < 8; ++i) {
            const int m = m0 + (ty << 3) + i;
            const int b = m >> 11;           // /T
            const int t = m & 2047;          // %T
            const float2 p0 = unpack2(acc[i][0]), p1 = unpack2(acc[i][1]);
            const float2 p2 = unpack2(acc[i][2]), p3 = unpack2(acc[i][3]);
            *(float4*)(dst + (((size_t)b * Hv + h0)     * Tv + t) * HDv + (tx << 2)) =
                make_float4(p0.x, p0.y, p1.x, p1.y);
            *(float4*)(dst + (((size_t)b * Hv + h0 + 1) * Tv + t) * HDv + (tx << 2)) =
                make_float4(p2.x, p2.y, p3.x, p3.y);
        }
    } else {
        #pragma unroll
        for (int i = 0; i < 8; ++i) {
            const int m = m0 + (ty << 3) + i;
            float* p = Cout + (size_t)m * N + n0 + (tx << 2);
            const float2 p0 = unpack2(acc[i][0]), p1 = unpack2(acc[i][1]);
            const float2 p2 = unpack2(acc[i][2]), p3 = unpack2(acc[i][3]);
            *(float4*)(p)      = make_float4(p0.x, p0.y, p1.x, p1.y);
            *(float4*)(p + 64) = make_float4(p2.x, p2.y, p3.x, p3.y);
        }
    }
}

// ---------------------------------------------------------------------------
// Causal flash attention, fp32 (f32x2 packed math), 128(q) x 64(k) tiles.
// 256 threads: tx -> 4 keys / 4 d-cols, ty -> 8 q rows. Online softmax with
// shfl_xor reductions within half-warps. 96KB dyn smem -> 2 CTAs/SM.
// ---------------------------------------------------------------------------
#define ATTN_SMEM_BYTES ((64*128 + 64*64 + 64*64 + 128*64) * 4)

__global__ __launch_bounds__(256, 2)
void attn_kernel()
{
    extern __shared__ float sm[];
    float* Qst = sm;                    // [d:64][q:128]
    float* Ks  = Qst + 64 * 128;        // [d:64][key:64]
    float* Vs  = Ks  + 64 * 64;         // [key:64][d:64]
    float* Ss  = Vs  + 64 * 64;         // [q:128][key:64]

    const int tid = threadIdx.x;
    const int tx  = tid & 15;
    const int ty  = tid >> 4;
    // Longest q-tiles first for wave balance
    const int qt = (int)gridDim.x - 1 - (int)blockIdx.x;
    const int bh = blockIdx.y;
    const int b  = bh >> 4;
    const int h  = bh & 15;
    const size_t plane = (size_t)bh * Tv * HDv;
    const int q0 = qt * 128;

    // Load Q tile transposed: Qst[d][qrow]
    {
        const int qrow = tid & 127;
        const int dh   = (tid >> 7) << 5;   // 0 or 32
        const float* qsrc = g_q + plane + (size_t)(q0 + qrow) * HDv + dh;
        #pragma unroll
        for (int c = 0; c < 8; ++c) {
            const float4 v = *(const float4*)(qsrc + (c << 2));
            Qst[(dh + (c << 2) + 0) * 128 + qrow] = v.x;
            Qst[(dh + (c << 2) + 1) * 128 + qrow] = v.y;
            Qst[(dh + (c << 2) + 2) * 128 + qrow] = v.z;
            Qst[(dh + (c << 2) + 3) * 128 + qrow] = v.w;
        }
    }

    u64t o2[8][2] = {};                 // packed O accumulators (4 d-cols)
    float mrow[8], lrow[8];
    #pragma unroll
    for (int i = 0; i < 8; ++i) { mrow[i] = -CUDART_INF_F; lrow[i] = 0.f; }

    const int keyl = tid & 63;
    const int dbl  = (tid >> 6) << 4;   // 0,16,32,48
    const int ktmax = 2 * qt + 1;       // last k-tile overlapping this q-tile

    for (int kt = 0; kt <= ktmax; ++kt) {
        const int k0 = kt * 64;

        __syncthreads();  // prev-iter Ss/Vs reads and Ks/Qst reads complete

        // K tile transposed: Ks[d][key]
        {
            const float* ksrc = g_k + plane + (size_t)(k0 + keyl) * HDv + dbl;
            #pragma unroll
            for (int c = 0; c < 4; ++c) {
                const float4 v = *(const float4*)(ksrc + (c << 2));
                Ks[(dbl + (c << 2) + 0) * 64 + keyl] = v.x;
                Ks[(dbl + (c << 2) + 1) * 64 + keyl] = v.y;
                Ks[(dbl + (c << 2) + 2) * 64 + keyl] = v.z;
                Ks[(dbl + (c << 2) + 3) * 64 + keyl] = v.w;
            }
        }
        // V tile flat copy: Vs[key][d]
        {
            const float4* vsrc = (const float4*)(g_v + plane + (size_t)k0 * HDv);
            float4* vd = (float4*)Vs;
            #pragma unroll
            for (int c = 0; c < 4; ++c) vd[tid + 256 * c] = vsrc[tid + 256 * c];
        }
        __syncthreads();

        // S = Q K^T : packed pairs along key; 16 FMA2 per d
        u64t s2[8][2] = {};
        #pragma unroll 8
        for (int d = 0; d < 64; ++d) {
            const ulonglong2 kp = *(const ulonglong2*)(&Ks[d * 64 + (tx << 2)]);
            const float4 qf0 = *(const float4*)(&Qst[d * 128 + (ty << 3)]);
            const float4 qf1 = *(const float4*)(&Qst[d * 128 + (ty << 3) + 4]);
            const float qa[8] = {qf0.x, qf0.y, qf0.z, qf0.w,
                                 qf1.x, qf1.y, qf1.z, qf1.w};
            #pragma unroll
            for (int i = 0; i < 8; ++i) {
                const u64t qs = splat2(qa[i]);
                fma2(s2[i][0], qs, kp.x);
                fma2(s2[i][1], qs, kp.y);
            }
        }

        // Unpack, scale, mask, online softmax (shfl across tx lanes)
        #pragma unroll
        for (int i = 0; i < 8; ++i) {
            const float2 u0 = unpack2(s2[i][0]);
            const float2 u1 = unpack2(s2[i][1]);
            float s[4] = {u0.x, u0.y, u1.x, u1.y};
            const int qg = q0 + (ty << 3) + i;
            const int kg = k0 + (tx << 2);
            #pragma unroll
            for (int j = 0; j < 4; ++j) {
                const float v = s[j] * 0.125f;   // 1/sqrt(64)
                s[j] = (kg + j > qg) ? -CUDART_INF_F : v;
            }
            float mx = fmaxf(fmaxf(s[0], s[1]), fmaxf(s[2], s[3]));
            #pragma unroll
            for (int off = 1; off < 16; off <<= 1)
                mx = fmaxf(mx, __shfl_xor_sync(0xffffffffu, mx, off));
            const float mnew  = fmaxf(mrow[i], mx);
            const float alpha = __expf(mrow[i] - mnew);  // 0 on first tile
            mrow[i] = mnew;

            float sum = 0.f;
            #pragma unroll
            for (int j = 0; j < 4; ++j) {
                const float p = __expf(s[j] - mnew);     // masked -> 0
                s[j] = p;
                sum += p;
            }
            #pragma unroll
            for (int off = 1; off < 16; off <<= 1)
                sum += __shfl_xor_sync(0xffffffffu, sum, off);
            lrow[i] = lrow[i] * alpha + sum;

            const u64t al2 = splat2(alpha);
            mul2(o2[i][0], al2);
            mul2(o2[i][1], al2);

            *(float4*)(&Ss[((ty << 3) + i) * 64 + (tx << 2)]) =
                make_float4(s[0], s[1], s[2], s[3]);
        }
        __syncthreads();  // P + V visible

        // O += P @ V : 16 FMA2 per key
        #pragma unroll 8
        for (int k = 0; k < 64; ++k) {
            const ulonglong2 vp = *(const ulonglong2*)(&Vs[k * 64 + (tx << 2)]);
            float p[8];
            #pragma unroll
            for (int i = 0; i < 8; ++i) p[i] = Ss[((ty << 3) + i) * 64 + k];
            #pragma unroll
            for (int i = 0; i < 8; ++i) {
                const u64t ps = splat2(p[i]);
                fma2(o2[i][0], ps, vp.x);
                fma2(o2[i][1], ps, vp.y);
            }
        }
    }

    // Epilogue: normalize, write [B,T,C] (merged heads)
    #pragma unroll
    for (int i = 0; i < 8; ++i) {
        const float inv = 1.0f / lrow[i];
        const int t = q0 + (ty << 3) + i;
        const float2 a = unpack2(o2[i][0]);
        const float2 c = unpack2(o2[i][1]);
        *(float4*)(g_att + ((size_t)(b * Tv + t)) * Cv + h * HDv + (tx << 2)) =
            make_float4(a.x * inv, a.y * inv, c.x * inv, c.y * inv);
    }
}

// ---------------------------------------------------------------------------
extern "C" void kernel_launch(void* const* d_in, const int* in_sizes, int n_in,
                              void* d_out, int out_size)
{
    const float* x      = (const float*)d_in[0];   // [B,T,C]
    const float* w_qkv  = (const float*)d_in[1];   // [C, 3C]
    const float* w_proj = (const float*)d_in[2];   // [C, C]
    float* out = (float*)d_out;                    // [B,T,C]

    // Opt-in >48KB dynamic smem for attention (host-side, capturable)
    cudaFuncSetAttribute(attn_kernel,
                         cudaFuncAttributeMaxDynamicSharedMemorySize,
                         ATTN_SMEM_BYTES);

    const dim3 blk(256);

    // 1) qkv = x @ w_qkv, scattered into g_q/g_k/g_v [B,H,T,HD]
    gemm128_kernel<0><<<dim3(C3 / 128, NTOK / 128), blk>>>(
        x, w_qkv, nullptr, NTOK, C3, Cv);

    // 2) causal flash attention -> g_att [B,T,C]
    attn_kernel<<<dim3(Tv / 128, Bv * Hv), blk, ATTN_SMEM_BYTES>>>();

    // 3) out = g_att @ w_proj
    gemm128_kernel<1><<<dim3(Cv / 128, NTOK / 128), blk>>>(
        nullptr, w_proj, out, NTOK, Cv, Cv);
}